// round 1
// baseline (speedup 1.0000x reference)
#include <cuda_runtime.h>

#define N_NODES 20000
#define N_EDGES 256000
#define DIM 128
#define DD (DIM*DIM)

// ---------------- scratch (static device memory; no allocations) ----------------
__device__ float  g_h   [N_NODES * DIM];          // current node features
__device__ float  g_e   [N_EDGES * DIM];          // current edge features
__device__ float  g_abde[N_NODES * 4 * DIM];      // [node][ A(0:128) | B(128:256) | D(256:384) | E(384:512) ]
__device__ float  g_enew[N_EDGES * DIM];          // pre-BN edge output
__device__ float  g_hnew[N_NODES * DIM];          // pre-BN node output
__device__ float  g_num [N_NODES * DIM];          // segment sum sigma*Bh[src]
__device__ float  g_den [N_NODES * DIM];          // segment sum sigma
__device__ double g_stats[4 * DIM];               // h_sum | h_sumsq | e_sum | e_sumsq
__device__ float  g_bn  [4 * DIM];                // h_scale | h_shift | e_scale | e_shift

// ---------------- zero per-layer accumulators ----------------
__global__ void k_zero() {
    int i = blockIdx.x * blockDim.x + threadIdx.x;
    if (i < N_NODES * DIM) { g_num[i] = 0.f; g_den[i] = 0.f; }
    if (i < 4 * DIM) g_stats[i] = 0.0;
}

// ---------------- shared SGEMM mainloop: C(128x128 tile) = A[M,128] @ B[128,128] ----------------
// 256 threads, BM=BN=128, BK=16, 8x8 per thread.
__device__ __forceinline__ void gemm_mainloop(
    const float* __restrict__ A, const float* __restrict__ B,
    int M, int row0, float (&acc)[8][8],
    float (*As)[DIM], float (*Bs)[DIM])
{
    const int tid = threadIdx.x;
    const int ty = tid >> 4, tx = tid & 15;
    // A tile: 128 rows x 16 cols = 512 float4 slots; thread handles slots tid, tid+256
    const int ar0 = tid >> 2,          ac0 = (tid & 3) << 2;
    const int ar1 = (tid + 256) >> 2,  ac1 = (tid & 3) << 2;
    // B tile: 16 rows x 128 cols = 512 float4 slots
    const int br0 = tid >> 5,          bc0 = (tid & 31) << 2;
    const int br1 = (tid + 256) >> 5,  bc1 = (tid & 31) << 2;

    #pragma unroll 1
    for (int kk = 0; kk < DIM; kk += 16) {
        float4 av0 = make_float4(0.f,0.f,0.f,0.f), av1 = make_float4(0.f,0.f,0.f,0.f);
        int r0 = row0 + ar0, r1 = row0 + ar1;
        if (r0 < M) av0 = *(const float4*)&A[(size_t)r0 * DIM + kk + ac0];
        if (r1 < M) av1 = *(const float4*)&A[(size_t)r1 * DIM + kk + ac1];
        float4 bv0 = *(const float4*)&B[(kk + br0) * DIM + bc0];
        float4 bv1 = *(const float4*)&B[(kk + br1) * DIM + bc1];
        __syncthreads();
        As[ac0+0][ar0] = av0.x; As[ac0+1][ar0] = av0.y; As[ac0+2][ar0] = av0.z; As[ac0+3][ar0] = av0.w;
        As[ac1+0][ar1] = av1.x; As[ac1+1][ar1] = av1.y; As[ac1+2][ar1] = av1.z; As[ac1+3][ar1] = av1.w;
        *(float4*)&Bs[br0][bc0] = bv0;
        *(float4*)&Bs[br1][bc1] = bv1;
        __syncthreads();
        #pragma unroll
        for (int k = 0; k < 16; k++) {
            float a[8], b[8];
            *(float4*)(a)   = *(const float4*)&As[k][ty*8];
            *(float4*)(a+4) = *(const float4*)&As[k][ty*8+4];
            *(float4*)(b)   = *(const float4*)&Bs[k][tx*8];
            *(float4*)(b+4) = *(const float4*)&Bs[k][tx*8+4];
            #pragma unroll
            for (int i = 0; i < 8; i++)
                #pragma unroll
                for (int j = 0; j < 8; j++)
                    acc[i][j] = fmaf(a[i], b[j], acc[i][j]);
        }
    }
}

// ---------------- plain GEMM + bias (embeddings): which=0 -> g_h, which=1 -> g_e ----------------
__global__ void __launch_bounds__(256) k_gemm_plain(
    const float* __restrict__ A, const float* __restrict__ Bm,
    const float* __restrict__ bias, int M, int which)
{
    __shared__ float As[16][DIM];
    __shared__ float Bs[16][DIM];
    float acc[8][8] = {};
    int row0 = blockIdx.x * 128;
    gemm_mainloop(A, Bm, M, row0, acc, As, Bs);
    float* C = which ? g_e : g_h;
    int tx = threadIdx.x & 15, ty = threadIdx.x >> 4;
    int c0 = tx * 8;
    float4 b0 = *(const float4*)&bias[c0];
    float4 b1 = *(const float4*)&bias[c0+4];
    #pragma unroll
    for (int i = 0; i < 8; i++) {
        int r = row0 + ty*8 + i;
        if (r < M) {
            float4 v0 = make_float4(acc[i][0]+b0.x, acc[i][1]+b0.y, acc[i][2]+b0.z, acc[i][3]+b0.w);
            float4 v1 = make_float4(acc[i][4]+b1.x, acc[i][5]+b1.y, acc[i][6]+b1.z, acc[i][7]+b1.w);
            *(float4*)&C[(size_t)r * DIM + c0]     = v0;
            *(float4*)&C[(size_t)r * DIM + c0 + 4] = v1;
        }
    }
}

// ---------------- node GEMM: blockIdx.y selects (A,B,D,E); writes g_abde[ . , y*128 : ] ----------------
__global__ void __launch_bounds__(256) k_gemm_node(
    const float* __restrict__ W0, const float* __restrict__ W1,
    const float* __restrict__ W2, const float* __restrict__ W3,
    const float* __restrict__ b0p, const float* __restrict__ b1p,
    const float* __restrict__ b2p, const float* __restrict__ b3p)
{
    __shared__ float As[16][DIM];
    __shared__ float Bs[16][DIM];
    float acc[8][8] = {};
    int row0 = blockIdx.x * 128;
    int y = blockIdx.y;
    const float* W = (y == 0) ? W0 : (y == 1) ? W1 : (y == 2) ? W2 : W3;
    const float* bb = (y == 0) ? b0p : (y == 1) ? b1p : (y == 2) ? b2p : b3p;
    gemm_mainloop(g_h, W, N_NODES, row0, acc, As, Bs);
    int tx = threadIdx.x & 15, ty = threadIdx.x >> 4;
    int c0 = tx * 8;
    float4 v0b = *(const float4*)&bb[c0];
    float4 v1b = *(const float4*)&bb[c0+4];
    int coloff = y * DIM;
    #pragma unroll
    for (int i = 0; i < 8; i++) {
        int r = row0 + ty*8 + i;
        if (r < N_NODES) {
            float4 v0 = make_float4(acc[i][0]+v0b.x, acc[i][1]+v0b.y, acc[i][2]+v0b.z, acc[i][3]+v0b.w);
            float4 v1 = make_float4(acc[i][4]+v1b.x, acc[i][5]+v1b.y, acc[i][6]+v1b.z, acc[i][7]+v1b.w);
            *(float4*)&g_abde[(size_t)r * 512 + coloff + c0]     = v0;
            *(float4*)&g_abde[(size_t)r * 512 + coloff + c0 + 4] = v1;
        }
    }
}

// ---------------- edge GEMM + fused gather/sigmoid/scatter + e-BN stats ----------------
__global__ void __launch_bounds__(256) k_gemm_edge(
    const float* __restrict__ Cw, const float* __restrict__ Cb,
    const int* __restrict__ src, const int* __restrict__ dst)
{
    __shared__ float As[16][DIM];
    __shared__ float Bs[16][DIM];
    __shared__ float s_sum[DIM];
    __shared__ float s_sq[DIM];
    float acc[8][8] = {};
    int row0 = blockIdx.x * 128;   // N_EDGES divisible by 128
    gemm_mainloop(g_e, Cw, N_EDGES, row0, acc, As, Bs);

    int tid = threadIdx.x;
    if (tid < DIM) { s_sum[tid] = 0.f; s_sq[tid] = 0.f; }
    __syncthreads();

    int tx = tid & 15, ty = tid >> 4;
    int c0 = tx * 8;
    float cb[8];
    *(float4*)(cb)   = *(const float4*)&Cb[c0];
    *(float4*)(cb+4) = *(const float4*)&Cb[c0+4];
    float csum[8] = {}, csq[8] = {};

    #pragma unroll 1
    for (int i = 0; i < 8; i++) {
        int r = row0 + ty*8 + i;
        int sv = src[r], dv = dst[r];
        const float* Bp = &g_abde[(size_t)sv * 512 + 128 + c0];
        const float* Dp = &g_abde[(size_t)sv * 512 + 256 + c0];
        const float* Ep = &g_abde[(size_t)dv * 512 + 384 + c0];
        float bh[8], dh[8], eh[8], ev[8];
        *(float4*)(bh)   = *(const float4*)(Bp);
        *(float4*)(bh+4) = *(const float4*)(Bp+4);
        *(float4*)(dh)   = *(const float4*)(Dp);
        *(float4*)(dh+4) = *(const float4*)(Dp+4);
        *(float4*)(eh)   = *(const float4*)(Ep);
        *(float4*)(eh+4) = *(const float4*)(Ep+4);
        float* nump = &g_num[dv * DIM + c0];
        float* denp = &g_den[dv * DIM + c0];
        #pragma unroll
        for (int j = 0; j < 8; j++) {
            float v = acc[i][j] + cb[j] + dh[j] + eh[j];
            ev[j] = v;
            float sg = 1.f / (1.f + __expf(-v));
            atomicAdd(nump + j, sg * bh[j]);
            atomicAdd(denp + j, sg);
            csum[j] += v;
            csq[j]  += v * v;
        }
        *(float4*)&g_enew[(size_t)r * DIM + c0]     = *(float4*)(ev);
        *(float4*)&g_enew[(size_t)r * DIM + c0 + 4] = *(float4*)(ev+4);
    }
    #pragma unroll
    for (int j = 0; j < 8; j++) {
        atomicAdd(&s_sum[c0 + j], csum[j]);
        atomicAdd(&s_sq[c0 + j],  csq[j]);
    }
    __syncthreads();
    if (tid < DIM) {
        atomicAdd(&g_stats[2*DIM + tid], (double)s_sum[tid]);
        atomicAdd(&g_stats[3*DIM + tid], (double)s_sq[tid]);
    }
}

// ---------------- h_new = Ah + num/(den+1e-6); accumulate h-BN stats ----------------
__global__ void k_hnew_stats() {
    __shared__ float s_sum[DIM];
    __shared__ float s_sq[DIM];
    int tid = threadIdx.x;                 // 256 threads: 2 rows in flight
    if (tid < DIM) { s_sum[tid] = 0.f; s_sq[tid] = 0.f; }
    __syncthreads();
    int col = tid & 127;
    int rh = tid >> 7;
    int row0 = blockIdx.x * 16;
    float lsum = 0.f, lsq = 0.f;
    for (int i = rh; i < 16; i += 2) {
        int r = row0 + i;
        if (r < N_NODES) {
            float a  = g_abde[(size_t)r * 512 + col];     // Ah (bias included)
            float nu = g_num[r * DIM + col];
            float de = g_den[r * DIM + col];
            float v = a + nu / (de + 1e-6f);
            g_hnew[r * DIM + col] = v;
            lsum += v; lsq += v * v;
        }
    }
    atomicAdd(&s_sum[col], lsum);
    atomicAdd(&s_sq[col], lsq);
    __syncthreads();
    if (tid < DIM) {
        atomicAdd(&g_stats[tid],       (double)s_sum[tid]);
        atomicAdd(&g_stats[DIM + tid], (double)s_sq[tid]);
    }
}

// ---------------- finalize BN: scale/shift per column ----------------
__global__ void k_finalize(const float* __restrict__ gh, const float* __restrict__ bh,
                           const float* __restrict__ ge, const float* __restrict__ be)
{
    int t = threadIdx.x;
    if (t < DIM) {
        double mu  = g_stats[t] / (double)N_NODES;
        double var = g_stats[DIM + t] / (double)N_NODES - mu * mu;
        double rstd = 1.0 / sqrt(var + 1e-5);
        float sc = gh[t] * (float)rstd;
        g_bn[t] = sc;
        g_bn[DIM + t] = bh[t] - (float)mu * sc;
    } else if (t < 2 * DIM) {
        int c = t - DIM;
        double mu  = g_stats[2*DIM + c] / (double)N_EDGES;
        double var = g_stats[3*DIM + c] / (double)N_EDGES - mu * mu;
        double rstd = 1.0 / sqrt(var + 1e-5);
        float sc = ge[c] * (float)rstd;
        g_bn[2*DIM + c] = sc;
        g_bn[3*DIM + c] = be[c] - (float)mu * sc;
    }
}

// ---------------- apply BN + relu + residual ----------------
__global__ void k_apply_h() {
    int i4 = blockIdx.x * blockDim.x + threadIdx.x;
    if (i4 < N_NODES * DIM / 4) {
        int c4 = (i4 & 31) * 4;
        float4 v  = *(const float4*)&g_hnew[i4 * 4];
        float4 sc = *(const float4*)&g_bn[c4];
        float4 sh = *(const float4*)&g_bn[DIM + c4];
        float4 hv = *(const float4*)&g_h[i4 * 4];
        hv.x += fmaxf(fmaf(v.x, sc.x, sh.x), 0.f);
        hv.y += fmaxf(fmaf(v.y, sc.y, sh.y), 0.f);
        hv.z += fmaxf(fmaf(v.z, sc.z, sh.z), 0.f);
        hv.w += fmaxf(fmaf(v.w, sc.w, sh.w), 0.f);
        *(float4*)&g_h[i4 * 4] = hv;
    }
}

__global__ void k_apply_e() {
    int i4 = blockIdx.x * blockDim.x + threadIdx.x;
    if (i4 < N_EDGES * DIM / 4) {
        int c4 = (i4 & 31) * 4;
        float4 v  = *(const float4*)&g_enew[(size_t)i4 * 4];
        float4 sc = *(const float4*)&g_bn[2*DIM + c4];
        float4 sh = *(const float4*)&g_bn[3*DIM + c4];
        float4 evv = *(const float4*)&g_e[(size_t)i4 * 4];
        evv.x += fmaxf(fmaf(v.x, sc.x, sh.x), 0.f);
        evv.y += fmaxf(fmaf(v.y, sc.y, sh.y), 0.f);
        evv.z += fmaxf(fmaf(v.z, sc.z, sh.z), 0.f);
        evv.w += fmaxf(fmaf(v.w, sc.w, sh.w), 0.f);
        *(float4*)&g_e[(size_t)i4 * 4] = evv;
    }
}

// ---------------- host launch ----------------
extern "C" void kernel_launch(void* const* d_in, const int* in_sizes, int n_in,
                              void* d_out, int out_size)
{
    const float* h0  = (const float*)d_in[0];
    const float* e0  = (const float*)d_in[1];
    const int*   src = (const int*)  d_in[2];
    const int*   dst = (const int*)  d_in[3];
    const float* Wh  = (const float*)d_in[4];
    const float* bhe = (const float*)d_in[5];
    const float* We  = (const float*)d_in[6];
    const float* bee = (const float*)d_in[7];
    const float* Aw  = (const float*)d_in[8];
    const float* Ab  = (const float*)d_in[9];
    const float* Bw  = (const float*)d_in[10];
    const float* Bb  = (const float*)d_in[11];
    const float* Cw  = (const float*)d_in[12];
    const float* Cb  = (const float*)d_in[13];
    const float* Dw  = (const float*)d_in[14];
    const float* Db  = (const float*)d_in[15];
    const float* Ew  = (const float*)d_in[16];
    const float* Eb  = (const float*)d_in[17];
    const float* gh  = (const float*)d_in[18];
    const float* bh  = (const float*)d_in[19];
    const float* ge  = (const float*)d_in[20];
    const float* be  = (const float*)d_in[21];

    const int grid_node = (N_NODES + 127) / 128;   // 157
    const int grid_edge = N_EDGES / 128;           // 2000

    // input embeddings
    k_gemm_plain<<<grid_node, 256>>>(h0, Wh, bhe, N_NODES, 0);
    k_gemm_plain<<<grid_edge, 256>>>(e0, We, bee, N_EDGES, 1);

    for (int l = 0; l < 4; l++) {
        k_zero<<<(N_NODES * DIM + 255) / 256, 256>>>();
        k_gemm_node<<<dim3(grid_node, 4), 256>>>(
            Aw + l*DD, Bw + l*DD, Dw + l*DD, Ew + l*DD,
            Ab + l*DIM, Bb + l*DIM, Db + l*DIM, Eb + l*DIM);
        k_gemm_edge<<<grid_edge, 256>>>(Cw + l*DD, Cb + l*DIM, src, dst);
        k_hnew_stats<<<(N_NODES + 15) / 16, 256>>>();
        k_finalize<<<1, 256>>>(gh + l*DIM, bh + l*DIM, ge + l*DIM, be + l*DIM);
        k_apply_h<<<(N_NODES * DIM / 4 + 255) / 256, 256>>>();
        if (l < 3)  // final e is dead — h output doesn't depend on it
            k_apply_e<<<(N_EDGES * DIM / 4 + 255) / 256, 256>>>();
    }

    cudaMemcpyFromSymbolAsync(d_out, g_h, sizeof(float) * N_NODES * DIM, 0,
                              cudaMemcpyDeviceToDevice, 0);
}

// round 2
// speedup vs baseline: 1.2028x; 1.2028x over previous
#include <cuda_runtime.h>

#define N_NODES 20000
#define N_EDGES 256000
#define DIM 128
#define DD (DIM*DIM)

// ---------------- scratch (static device memory; no allocations) ----------------
__device__ float  g_h   [N_NODES * DIM];
__device__ float  g_e   [N_EDGES * DIM];
__device__ float  g_abde[N_NODES * 4 * DIM];   // [node][ A | B | D | E ]
__device__ float  g_enew[N_EDGES * DIM];
__device__ float  g_hnew[N_NODES * DIM];
__device__ double g_stats[4 * DIM];            // h_sum | h_sumsq | e_sum | e_sumsq
__device__ float  g_bn  [4 * DIM];             // h_scale | h_shift | e_scale | e_shift
// CSR for dst-grouped edges (built once per call)
__device__ int    g_cnt [N_NODES];
__device__ int    g_cnt2[N_NODES];
__device__ int    g_csr [N_NODES + 1];
__device__ int    g_perm[N_EDGES];
__device__ int    g_srcp[N_EDGES];

// ================= CSR build =================
__global__ void k_zero_cnt() {
    int i = blockIdx.x * blockDim.x + threadIdx.x;
    if (i < N_NODES) { g_cnt[i] = 0; g_cnt2[i] = 0; }
}
__global__ void k_hist(const int* __restrict__ dst) {
    int e = blockIdx.x * blockDim.x + threadIdx.x;
    if (e < N_EDGES) atomicAdd(&g_cnt[dst[e]], 1);
}
__global__ void k_scan() {   // single block, 1024 threads, chunk of 20 each
    __shared__ int s[1024];
    int t = threadIdx.x;
    int base = t * 20;
    int loc[20];
    int sum = 0;
    #pragma unroll
    for (int j = 0; j < 20; j++) {
        int idx = base + j;
        loc[j] = sum;
        if (idx < N_NODES) sum += g_cnt[idx];
    }
    s[t] = sum;
    __syncthreads();
    for (int off = 1; off < 1024; off <<= 1) {
        int v = (t >= off) ? s[t - off] : 0;
        __syncthreads();
        s[t] += v;
        __syncthreads();
    }
    int pre = (t > 0) ? s[t - 1] : 0;
    #pragma unroll
    for (int j = 0; j < 20; j++) {
        int idx = base + j;
        if (idx < N_NODES) g_csr[idx] = pre + loc[j];
    }
    if (t == 1023) g_csr[N_NODES] = s[1023];
}
__global__ void k_scatter(const int* __restrict__ src, const int* __restrict__ dst) {
    int e = blockIdx.x * blockDim.x + threadIdx.x;
    if (e < N_EDGES) {
        int d = dst[e];
        int pos = g_csr[d] + atomicAdd(&g_cnt2[d], 1);
        g_perm[pos] = e;
        g_srcp[pos] = src[e];
    }
}

__global__ void k_zero_stats() {
    int i = threadIdx.x;
    if (i < 4 * DIM) g_stats[i] = 0.0;
}

// ================= double-buffered SGEMM mainloop =================
// 256 threads, BM=BN=128, BK=16, 8x8 per thread, 1 sync per k-iter.
__device__ __forceinline__ void gemm_mainloop(
    const float* __restrict__ A, const float* __restrict__ B,
    int M, int row0, float (&acc)[8][8],
    float (*As)[16][DIM], float (*Bs)[16][DIM])
{
    const int tid = threadIdx.x;
    const int ty = tid >> 4, tx = tid & 15;
    const int ar0 = tid >> 2, ac0 = (tid & 3) << 2;
    const int ar1 = ar0 + 64;
    const int br0 = tid >> 5, bc0 = (tid & 31) << 2;
    const int br1 = br0 + 8;
    const int r0 = row0 + ar0, r1 = row0 + ar1;
    const float4 z4 = make_float4(0.f, 0.f, 0.f, 0.f);

    float4 av0, av1, bv0, bv1;

    // iter 0 load + store
    av0 = (r0 < M) ? *(const float4*)&A[(size_t)r0 * DIM + ac0] : z4;
    av1 = (r1 < M) ? *(const float4*)&A[(size_t)r1 * DIM + ac0] : z4;
    bv0 = *(const float4*)&B[br0 * DIM + bc0];
    bv1 = *(const float4*)&B[br1 * DIM + bc0];
    As[0][ac0+0][ar0] = av0.x; As[0][ac0+1][ar0] = av0.y; As[0][ac0+2][ar0] = av0.z; As[0][ac0+3][ar0] = av0.w;
    As[0][ac0+0][ar1] = av1.x; As[0][ac0+1][ar1] = av1.y; As[0][ac0+2][ar1] = av1.z; As[0][ac0+3][ar1] = av1.w;
    *(float4*)&Bs[0][br0][bc0] = bv0;
    *(float4*)&Bs[0][br1][bc0] = bv1;
    __syncthreads();

    // prefetch iter 1
    av0 = (r0 < M) ? *(const float4*)&A[(size_t)r0 * DIM + 16 + ac0] : z4;
    av1 = (r1 < M) ? *(const float4*)&A[(size_t)r1 * DIM + 16 + ac0] : z4;
    bv0 = *(const float4*)&B[(16 + br0) * DIM + bc0];
    bv1 = *(const float4*)&B[(16 + br1) * DIM + bc0];

    #pragma unroll 1
    for (int it = 0; it < 8; it++) {
        const int cur = it & 1;
        #pragma unroll
        for (int k = 0; k < 16; k++) {
            float a[8], b[8];
            *(float4*)(a)   = *(const float4*)&As[cur][k][ty*8];
            *(float4*)(a+4) = *(const float4*)&As[cur][k][ty*8+4];
            *(float4*)(b)   = *(const float4*)&Bs[cur][k][tx*8];
            *(float4*)(b+4) = *(const float4*)&Bs[cur][k][tx*8+4];
            #pragma unroll
            for (int i = 0; i < 8; i++)
                #pragma unroll
                for (int j = 0; j < 8; j++)
                    acc[i][j] = fmaf(a[i], b[j], acc[i][j]);
        }
        if (it < 7) {
            const int nxt = cur ^ 1;
            As[nxt][ac0+0][ar0] = av0.x; As[nxt][ac0+1][ar0] = av0.y; As[nxt][ac0+2][ar0] = av0.z; As[nxt][ac0+3][ar0] = av0.w;
            As[nxt][ac0+0][ar1] = av1.x; As[nxt][ac0+1][ar1] = av1.y; As[nxt][ac0+2][ar1] = av1.z; As[nxt][ac0+3][ar1] = av1.w;
            *(float4*)&Bs[nxt][br0][bc0] = bv0;
            *(float4*)&Bs[nxt][br1][bc0] = bv1;
            __syncthreads();
            if (it < 6) {
                int kk = (it + 2) * 16;
                av0 = (r0 < M) ? *(const float4*)&A[(size_t)r0 * DIM + kk + ac0] : z4;
                av1 = (r1 < M) ? *(const float4*)&A[(size_t)r1 * DIM + kk + ac0] : z4;
                bv0 = *(const float4*)&B[(kk + br0) * DIM + bc0];
                bv1 = *(const float4*)&B[(kk + br1) * DIM + bc0];
            }
        }
    }
}

// ---------------- plain GEMM + bias (embeddings) ----------------
__global__ void __launch_bounds__(256) k_gemm_plain(
    const float* __restrict__ A, const float* __restrict__ Bm,
    const float* __restrict__ bias, int M, int which)
{
    __shared__ float As[2][16][DIM];
    __shared__ float Bs[2][16][DIM];
    float acc[8][8] = {};
    int row0 = blockIdx.x * 128;
    gemm_mainloop(A, Bm, M, row0, acc, As, Bs);
    float* C = which ? g_e : g_h;
    int tx = threadIdx.x & 15, ty = threadIdx.x >> 4;
    int c0 = tx * 8;
    float4 b0 = *(const float4*)&bias[c0];
    float4 b1 = *(const float4*)&bias[c0+4];
    #pragma unroll
    for (int i = 0; i < 8; i++) {
        int r = row0 + ty*8 + i;
        if (r < M) {
            float4 v0 = make_float4(acc[i][0]+b0.x, acc[i][1]+b0.y, acc[i][2]+b0.z, acc[i][3]+b0.w);
            float4 v1 = make_float4(acc[i][4]+b1.x, acc[i][5]+b1.y, acc[i][6]+b1.z, acc[i][7]+b1.w);
            *(float4*)&C[(size_t)r * DIM + c0]     = v0;
            *(float4*)&C[(size_t)r * DIM + c0 + 4] = v1;
        }
    }
}

// ---------------- node GEMM: blockIdx.y selects (A,B,D,E) ----------------
__global__ void __launch_bounds__(256) k_gemm_node(
    const float* __restrict__ W0, const float* __restrict__ W1,
    const float* __restrict__ W2, const float* __restrict__ W3,
    const float* __restrict__ b0p, const float* __restrict__ b1p,
    const float* __restrict__ b2p, const float* __restrict__ b3p)
{
    __shared__ float As[2][16][DIM];
    __shared__ float Bs[2][16][DIM];
    float acc[8][8] = {};
    int row0 = blockIdx.x * 128;
    int y = blockIdx.y;
    const float* W  = (y == 0) ? W0  : (y == 1) ? W1  : (y == 2) ? W2  : W3;
    const float* bb = (y == 0) ? b0p : (y == 1) ? b1p : (y == 2) ? b2p : b3p;
    gemm_mainloop(g_h, W, N_NODES, row0, acc, As, Bs);
    int tx = threadIdx.x & 15, ty = threadIdx.x >> 4;
    int c0 = tx * 8;
    float4 v0b = *(const float4*)&bb[c0];
    float4 v1b = *(const float4*)&bb[c0+4];
    int coloff = y * DIM;
    #pragma unroll
    for (int i = 0; i < 8; i++) {
        int r = row0 + ty*8 + i;
        if (r < N_NODES) {
            float4 v0 = make_float4(acc[i][0]+v0b.x, acc[i][1]+v0b.y, acc[i][2]+v0b.z, acc[i][3]+v0b.w);
            float4 v1 = make_float4(acc[i][4]+v1b.x, acc[i][5]+v1b.y, acc[i][6]+v1b.z, acc[i][7]+v1b.w);
            *(float4*)&g_abde[(size_t)r * 512 + coloff + c0]     = v0;
            *(float4*)&g_abde[(size_t)r * 512 + coloff + c0 + 4] = v1;
        }
    }
}

// ---------------- edge GEMM + fused gather + e-BN stats (no atomics to num/den) ----------------
__global__ void __launch_bounds__(256) k_gemm_edge(
    const float* __restrict__ Cw, const float* __restrict__ Cb,
    const int* __restrict__ src, const int* __restrict__ dst)
{
    __shared__ float As[2][16][DIM];
    __shared__ float Bs[2][16][DIM];
    __shared__ float s_sum[DIM];
    __shared__ float s_sq[DIM];
    float acc[8][8] = {};
    int row0 = blockIdx.x * 128;   // N_EDGES divisible by 128
    gemm_mainloop(g_e, Cw, N_EDGES, row0, acc, As, Bs);

    int tid = threadIdx.x;
    if (tid < DIM) { s_sum[tid] = 0.f; s_sq[tid] = 0.f; }
    __syncthreads();

    int tx = tid & 15, ty = tid >> 4;
    int c0 = tx * 8;
    float cb[8];
    *(float4*)(cb)   = *(const float4*)&Cb[c0];
    *(float4*)(cb+4) = *(const float4*)&Cb[c0+4];
    float csum[8] = {}, csq[8] = {};

    #pragma unroll 1
    for (int i = 0; i < 8; i++) {
        int r = row0 + ty*8 + i;
        int sv = src[r], dv = dst[r];
        const float* Dp = &g_abde[(size_t)sv * 512 + 256 + c0];
        const float* Ep = &g_abde[(size_t)dv * 512 + 384 + c0];
        float dh[8], eh[8], ev[8];
        *(float4*)(dh)   = *(const float4*)(Dp);
        *(float4*)(dh+4) = *(const float4*)(Dp+4);
        *(float4*)(eh)   = *(const float4*)(Ep);
        *(float4*)(eh+4) = *(const float4*)(Ep+4);
        #pragma unroll
        for (int j = 0; j < 8; j++) {
            float v = acc[i][j] + cb[j] + dh[j] + eh[j];
            ev[j] = v;
            csum[j] += v;
            csq[j]  += v * v;
        }
        *(float4*)&g_enew[(size_t)r * DIM + c0]     = *(float4*)(ev);
        *(float4*)&g_enew[(size_t)r * DIM + c0 + 4] = *(float4*)(ev+4);
    }
    #pragma unroll
    for (int j = 0; j < 8; j++) {
        atomicAdd(&s_sum[c0 + j], csum[j]);
        atomicAdd(&s_sq[c0 + j],  csq[j]);
    }
    __syncthreads();
    if (tid < DIM) {
        atomicAdd(&g_stats[2*DIM + tid], (double)s_sum[tid]);
        atomicAdd(&g_stats[3*DIM + tid], (double)s_sq[tid]);
    }
}

// ---------------- per-node aggregation (CSR, no atomics): h_new = Ah + num/(den+eps) ----------------
__global__ void __launch_bounds__(128) k_aggregate() {
    int n = blockIdx.x;
    int t = threadIdx.x;
    int beg = g_csr[n], end = g_csr[n + 1];
    float num = 0.f, den = 0.f;
    for (int i = beg; i < end; i++) {
        int e = g_perm[i];
        int s = g_srcp[i];
        float v = g_enew[(size_t)e * DIM + t];
        float bh = g_abde[(size_t)s * 512 + 128 + t];
        float sg = 1.f / (1.f + __expf(-v));
        num = fmaf(sg, bh, num);
        den += sg;
    }
    float hv = g_abde[(size_t)n * 512 + t] + num / (den + 1e-6f);
    g_hnew[n * DIM + t] = hv;
}

// ---------------- h-BN stats over g_hnew ----------------
__global__ void __launch_bounds__(256) k_hstats() {
    __shared__ float s_sum[DIM];
    __shared__ float s_sq[DIM];
    int tid = threadIdx.x;
    if (tid < DIM) { s_sum[tid] = 0.f; s_sq[tid] = 0.f; }
    __syncthreads();
    int col = tid & 127;
    int rh = tid >> 7;
    int row0 = blockIdx.x * 128;
    float ls = 0.f, lq = 0.f;
    for (int i = rh; i < 128; i += 2) {
        int r = row0 + i;
        if (r < N_NODES) {
            float v = g_hnew[r * DIM + col];
            ls += v; lq += v * v;
        }
    }
    atomicAdd(&s_sum[col], ls);
    atomicAdd(&s_sq[col], lq);
    __syncthreads();
    if (tid < DIM) {
        atomicAdd(&g_stats[tid],       (double)s_sum[tid]);
        atomicAdd(&g_stats[DIM + tid], (double)s_sq[tid]);
    }
}

// ---------------- finalize BN ----------------
__global__ void k_finalize(const float* __restrict__ gh, const float* __restrict__ bh,
                           const float* __restrict__ ge, const float* __restrict__ be)
{
    int t = threadIdx.x;
    if (t < DIM) {
        double mu  = g_stats[t] / (double)N_NODES;
        double var = g_stats[DIM + t] / (double)N_NODES - mu * mu;
        double rstd = 1.0 / sqrt(var + 1e-5);
        float sc = gh[t] * (float)rstd;
        g_bn[t] = sc;
        g_bn[DIM + t] = bh[t] - (float)mu * sc;
    } else if (t < 2 * DIM) {
        int c = t - DIM;
        double mu  = g_stats[2*DIM + c] / (double)N_EDGES;
        double var = g_stats[3*DIM + c] / (double)N_EDGES - mu * mu;
        double rstd = 1.0 / sqrt(var + 1e-5);
        float sc = ge[c] * (float)rstd;
        g_bn[2*DIM + c] = sc;
        g_bn[3*DIM + c] = be[c] - (float)mu * sc;
    }
}

// ---------------- apply BN + relu + residual ----------------
__global__ void k_apply_h() {
    int i4 = blockIdx.x * blockDim.x + threadIdx.x;
    if (i4 < N_NODES * DIM / 4) {
        int c4 = (i4 & 31) * 4;
        float4 v  = *(const float4*)&g_hnew[i4 * 4];
        float4 sc = *(const float4*)&g_bn[c4];
        float4 sh = *(const float4*)&g_bn[DIM + c4];
        float4 hv = *(const float4*)&g_h[i4 * 4];
        hv.x += fmaxf(fmaf(v.x, sc.x, sh.x), 0.f);
        hv.y += fmaxf(fmaf(v.y, sc.y, sh.y), 0.f);
        hv.z += fmaxf(fmaf(v.z, sc.z, sh.z), 0.f);
        hv.w += fmaxf(fmaf(v.w, sc.w, sh.w), 0.f);
        *(float4*)&g_h[i4 * 4] = hv;
    }
}
__global__ void k_apply_e() {
    int i4 = blockIdx.x * blockDim.x + threadIdx.x;
    if (i4 < N_EDGES * DIM / 4) {
        int c4 = (i4 & 31) * 4;
        float4 v  = *(const float4*)&g_enew[(size_t)i4 * 4];
        float4 sc = *(const float4*)&g_bn[2*DIM + c4];
        float4 sh = *(const float4*)&g_bn[3*DIM + c4];
        float4 evv = *(const float4*)&g_e[(size_t)i4 * 4];
        evv.x += fmaxf(fmaf(v.x, sc.x, sh.x), 0.f);
        evv.y += fmaxf(fmaf(v.y, sc.y, sh.y), 0.f);
        evv.z += fmaxf(fmaf(v.z, sc.z, sh.z), 0.f);
        evv.w += fmaxf(fmaf(v.w, sc.w, sh.w), 0.f);
        *(float4*)&g_e[(size_t)i4 * 4] = evv;
    }
}

// ---------------- host launch ----------------
extern "C" void kernel_launch(void* const* d_in, const int* in_sizes, int n_in,
                              void* d_out, int out_size)
{
    const float* h0  = (const float*)d_in[0];
    const float* e0  = (const float*)d_in[1];
    const int*   src = (const int*)  d_in[2];
    const int*   dst = (const int*)  d_in[3];
    const float* Wh  = (const float*)d_in[4];
    const float* bhe = (const float*)d_in[5];
    const float* We  = (const float*)d_in[6];
    const float* bee = (const float*)d_in[7];
    const float* Aw  = (const float*)d_in[8];
    const float* Ab  = (const float*)d_in[9];
    const float* Bw  = (const float*)d_in[10];
    const float* Bb  = (const float*)d_in[11];
    const float* Cw  = (const float*)d_in[12];
    const float* Cb  = (const float*)d_in[13];
    const float* Dw  = (const float*)d_in[14];
    const float* Db  = (const float*)d_in[15];
    const float* Ew  = (const float*)d_in[16];
    const float* Eb  = (const float*)d_in[17];
    const float* gh  = (const float*)d_in[18];
    const float* bh  = (const float*)d_in[19];
    const float* ge  = (const float*)d_in[20];
    const float* be  = (const float*)d_in[21];

    const int grid_node = (N_NODES + 127) / 128;   // 157
    const int grid_edge = N_EDGES / 128;           // 2000

    // CSR build (once per call; dst fixed)
    k_zero_cnt<<<(N_NODES + 255) / 256, 256>>>();
    k_hist<<<(N_EDGES + 255) / 256, 256>>>(dst);
    k_scan<<<1, 1024>>>();
    k_scatter<<<(N_EDGES + 255) / 256, 256>>>(src, dst);

    // input embeddings
    k_gemm_plain<<<grid_node, 256>>>(h0, Wh, bhe, N_NODES, 0);
    k_gemm_plain<<<grid_edge, 256>>>(e0, We, bee, N_EDGES, 1);

    for (int l = 0; l < 4; l++) {
        k_zero_stats<<<1, 512>>>();
        k_gemm_node<<<dim3(grid_node, 4), 256>>>(
            Aw + l*DD, Bw + l*DD, Dw + l*DD, Ew + l*DD,
            Ab + l*DIM, Bb + l*DIM, Db + l*DIM, Eb + l*DIM);
        k_gemm_edge<<<grid_edge, 256>>>(Cw + l*DD, Cb + l*DIM, src, dst);
        k_aggregate<<<N_NODES, 128>>>();
        k_hstats<<<grid_node, 256>>>();
        k_finalize<<<1, 256>>>(gh + l*DIM, bh + l*DIM, ge + l*DIM, be + l*DIM);
        k_apply_h<<<(N_NODES * DIM / 4 + 255) / 256, 256>>>();
        if (l < 3)
            k_apply_e<<<(N_EDGES * DIM / 4 + 255) / 256, 256>>>();
    }

    cudaMemcpyFromSymbolAsync(d_out, g_h, sizeof(float) * N_NODES * DIM, 0,
                              cudaMemcpyDeviceToDevice, 0);
}